// round 14
// baseline (speedup 1.0000x reference)
#include <cuda_runtime.h>
#include <math.h>
#include <stdint.h>

#define Bq 4
#define Nv 12000
#define FN 24000
#define C 128
#define NNZ (48 * FN)     // 1,152,000
#define EPSV 1e-5f

#define RV (Bq * Nv)      // 48000 vertex rows
#define RF (Bq * FN)      // 96000 face rows

#define BINS 98304        // 96 * 1024 (covers 96000 rows)
#define SMEM_DYN 34880    // dynamic smem union for gemm_body

// ---------------- scratch (device globals: allocation-free) ----------------
__device__ float  g_v[RV * C];
__device__ float  g_f[RF * C];
__device__ float  g_msg[RF * C];
__device__ float  g_x1[RV * C];                 // avg-block j0 output
__device__ double g_statsAll[33 * 512 + 16 * 512]; // statsL[33] then avgmsL[16]
__device__ double g_msum[Bq];                   // per-batch mask sums

// CSR build scratch (doubled: [0,BINS)=A, [BINS,2*BINS)=B)
__device__ int    g_cnt2[2 * BINS];
__device__ int    g_incl2[2 * BINS];
__device__ int    g_bsum2[192];
__device__ int    g_cursor2[2 * BINS];
__device__ int    g_startA[BINS + 1];
__device__ int    g_startB[BINS + 1];
__device__ float2 g_edgeA[NNZ];
__device__ float2 g_edgeB[NNZ];

__device__ __forceinline__ float elu_f(float x) {
    return x > 0.f ? x : expm1f(x);
}

// ================= fused dual-CSR build =================
__global__ void hist2_kernel(const int* __restrict__ rowsA,
                             const int* __restrict__ rowsB) {
    int i = blockIdx.x * blockDim.x + threadIdx.x;
    if (i < NNZ) atomicAdd(&g_cnt2[rowsA[i]], 1);
    else         atomicAdd(&g_cnt2[BINS + rowsB[i - NNZ]], 1);
}

__global__ void scan_block2_kernel() {
    __shared__ int sd[1024];
    int t = threadIdx.x;
    int gid = blockIdx.x * 1024 + t;
    sd[t] = g_cnt2[gid];
    __syncthreads();
    for (int off = 1; off < 1024; off <<= 1) {
        int add = (t >= off) ? sd[t - off] : 0;
        __syncthreads();
        sd[t] += add;
        __syncthreads();
    }
    g_incl2[gid] = sd[t];
    if (t == 1023) g_bsum2[blockIdx.x] = sd[1023];
}

__global__ void scan_top2_kernel() {
    int h = blockIdx.x;                   // 0 = A, 1 = B
    if (threadIdx.x == 0) {
        int run = 0;
        for (int b = h * 96; b < h * 96 + 96; b++) {
            int tt = g_bsum2[b]; g_bsum2[b] = run; run += tt;
        }
    }
}

__global__ void scan_finish2_kernel(int* __restrict__ startA,
                                    int* __restrict__ startB) {
    int t = threadIdx.x;
    int gid = blockIdx.x * 1024 + t;
    int half = gid >= BINS;
    int lid_ = gid - half * BINS;
    int* start = half ? startB : startA;
    int excl = g_incl2[gid] - g_cnt2[gid] + g_bsum2[blockIdx.x];
    start[lid_] = excl;
    g_cursor2[gid] = excl;
    if (lid_ == BINS - 1) start[BINS] = excl + g_cnt2[gid];
}

__global__ void fill2_kernel(const int* __restrict__ rowsA,
                             const int* __restrict__ colsA,
                             const float* __restrict__ valsA,
                             const int* __restrict__ rowsB,
                             const int* __restrict__ colsB,
                             const float* __restrict__ valsB,
                             float2* __restrict__ edgesA,
                             float2* __restrict__ edgesB) {
    int i = blockIdx.x * blockDim.x + threadIdx.x;
    if (i < NNZ) {
        int pos = atomicAdd(&g_cursor2[rowsA[i]], 1);
        edgesA[pos] = make_float2(valsA[i], __int_as_float(colsA[i]));
    } else {
        int j = i - NNZ;
        int pos = atomicAdd(&g_cursor2[BINS + rowsB[j]], 1);
        edgesB[pos] = make_float2(valsB[j], __int_as_float(colsB[j]));
    }
}

// ================= SpMM (CSR, atomic-free) =================
__global__ void spmm_kernel(const int* __restrict__ start,
                            const float2* __restrict__ edges,
                            const float* __restrict__ in, int inStride,
                            float* __restrict__ out, int outStride) {
    int t = threadIdx.x;
    int r = blockIdx.x * 4 + (t >> 5);
    int lane = t & 31;
    int b = lane >> 3, k4 = lane & 7;
    int s = start[r], e = start[r + 1];
    float4 acc = make_float4(0.f, 0.f, 0.f, 0.f);
    const float* inb = in + (size_t)b * inStride;
    for (int i = s; i < e; i++) {
        float2 ed = edges[i];
        int c = __float_as_int(ed.y);
        float4 q = *(const float4*)&inb[c * 32 + k4 * 4];
        acc.x = fmaf(ed.x, q.x, acc.x);
        acc.y = fmaf(ed.x, q.y, acc.y);
        acc.z = fmaf(ed.x, q.z, acc.z);
        acc.w = fmaf(ed.x, q.w, acc.w);
    }
    *(float4*)&out[(size_t)b * outStride + r * 32 + k4 * 4] = acc;
}

// 256-thread SpMM body for fused launches (8 rows per block)
__device__ void spmm_body(int bid, const int* __restrict__ start,
                          const float2* __restrict__ edges,
                          const float* __restrict__ in, int inStride,
                          float* __restrict__ out, int outStride) {
    int r = bid * 8 + (threadIdx.x >> 5);
    int lane = threadIdx.x & 31;
    int b = lane >> 3, k4 = lane & 7;
    int s = start[r], e = start[r + 1];
    float4 acc = make_float4(0.f, 0.f, 0.f, 0.f);
    const float* inb = in + (size_t)b * inStride;
    for (int i = s; i < e; i++) {
        float2 ed = edges[i];
        int c = __float_as_int(ed.y);
        float4 q = *(const float4*)&inb[c * 32 + k4 * 4];
        acc.x = fmaf(ed.x, q.x, acc.x);
        acc.y = fmaf(ed.x, q.y, acc.y);
        acc.z = fmaf(ed.x, q.z, acc.z);
        acc.w = fmaf(ed.x, q.w, acc.w);
    }
    *(float4*)&out[(size_t)b * outStride + r * 32 + k4 * 4] = acc;
}

// ================= conv1 (fused stats -> slot0 first half) =================
__global__ void conv1_kernel(const float* __restrict__ in,
                             const float* __restrict__ W1,
                             const float* __restrict__ b1,
                             double* __restrict__ st) {
    int c = threadIdx.x;                  // 128
    int r0 = blockIdx.x * 64;
    float w0 = W1[c], w1 = W1[128 + c], w2 = W1[256 + c], bb = b1[c];
    float s = 0.f, q = 0.f;
    for (int i = 0; i < 64; i++) {
        int r = r0 + i;
        float x0 = in[r * 3 + 0], x1 = in[r * 3 + 1], x2 = in[r * 3 + 2];
        float val = fmaf(x0, w0, fmaf(x1, w1, fmaf(x2, w2, bb)));
        g_v[(size_t)r * 128 + c] = val;
        float e = elu_f(val);
        s += e; q += e * e;
    }
    atomicAdd(&st[c], (double)s);
    atomicAdd(&st[256 + c], (double)q);
}

// ================= slim stats over msg (second-half channels) =================
__global__ void statsm_kernel(const float* __restrict__ x,
                              double* __restrict__ st) {
    int c = threadIdx.x;                  // 128
    int r0 = blockIdx.x * 64;
    float s = 0.f, q = 0.f;
    for (int i = 0; i < 64; i++) {
        float e = elu_f(x[(size_t)(r0 + i) * 128 + c]);
        s += e; q += e * e;
    }
    atomicAdd(&st[128 + c], (double)s);
    atomicAdd(&st[384 + c], (double)q);
}

// ================= per-batch mask sums =================
__global__ void masksum_kernel(const float* __restrict__ mask) {
    __shared__ float sd[256];
    int b = blockIdx.x, t = threadIdx.x;
    float s = 0.f;
    for (int i = t; i < Nv; i += 256) s += mask[b * Nv + i];
    sd[t] = s;
    __syncthreads();
    for (int off = 128; off; off >>= 1) {
        if (t < off) sd[t] += sd[t + off];
        __syncthreads();
    }
    if (t == 0) g_msum[b] = (double)sd[0];
}

// ================= GEMM body: 64x128 tile, 256 threads =================
// MODE 0: plain KD-channel GEMM.
// MODE 1 (avg): KD=128 live; channels 128-255 are per-batch broadcast consts
//   derived analytically from avgms; folded into per-batch bias bb via Wfold.
// MODE 2 (const): KD=128 live; other half is the constant beta_c (input == 0);
//   folded into batch-uniform bias via Wfold.
// Dynamic smem union (SMEM_DYN bytes): As[0,8192) Bs[8192,24576) sc/sh[24576,26624)
//   xh2s[26624,28672) bbp[28672,32768) bbs[32768,34816) rbarr[34816,34880)
template <int KD, int MODE, bool MSUM>
__device__ void gemm_body(
    int bid,
    const float* __restrict__ A0, const float* __restrict__ A1,
    const float* __restrict__ W, const float* __restrict__ bias,
    const float* __restrict__ res, float* __restrict__ out,
    const double* __restrict__ stats,
    const float* __restrict__ gamma, const float* __restrict__ beta,
    double invR, const double* __restrict__ avgms,
    const float* __restrict__ Wfold, const float* __restrict__ betac,
    double* __restrict__ statsOut, double* __restrict__ amOut,
    const float* __restrict__ mask) {
    extern __shared__ char sm[];
    float* As   = (float*)sm;
    float* Bs   = (float*)(sm + 8192);
    float* sc   = (float*)(sm + 24576);
    float* sh   = (float*)(sm + 25600);
    float* xh2s = (float*)(sm + 26624);        // [b*128+k]
    float* bbp  = (float*)(sm + 28672);        // [(h*4+b)*128+c] (MODE1) / [h*128+c] (MODE2)
    float* bbs  = (float*)(sm + 32768);        // [b*128+c]
    int*   rbarr = (int*)(sm + 34816);
    const int tid = threadIdx.x;
    const int row0 = bid * 64;

    // ---- prologue: BN scale/shift from stats slot ----
    if (tid < KD) {
        double mean = stats[tid] * invR;
        double var  = stats[256 + tid] * invR - mean * mean;
        if (var < 0.0) var = 0.0;
        double a = (double)gamma[tid] * rsqrt(var + (double)EPSV);
        sc[tid] = (float)a;
        sh[tid] = (float)((double)beta[tid] - mean * a);
    }
    if (MODE == 1 && tid < 128) {
        float af[Bq];
        double s = 0.0, sq = 0.0;
        for (int b = 0; b < Bq; b++) {
            af[b] = (float)(avgms[b * 128 + tid] / g_msum[b]);
            double m = (double)af[b];
            s  += m * (double)Nv;
            sq += m * m * (double)Nv;
        }
        double mean = s * (1.0 / (double)RV);
        double var  = sq * (1.0 / (double)RV) - mean * mean;
        if (var < 0.0) var = 0.0;
        double a = (double)gamma[128 + tid] * rsqrt(var + (double)EPSV);
        float sck = (float)a;
        float shk = (float)((double)beta[128 + tid] - mean * a);
#pragma unroll
        for (int b = 0; b < Bq; b++) xh2s[b * 128 + tid] = fmaf(af[b], sck, shk);
    }
    if (MODE == 2 && tid < 128) {
        // input identically 0 -> normalized value == beta_c (mean=0, var=0)
        xh2s[tid] = betac[tid];
    }

    const int arow = tid & 63;
    const int ksg  = (tid >> 6) * 4;
    const int bkr  = tid >> 4;
    const int bcx  = (tid & 15) * 4;
    const int ty = tid >> 4, tx = tid & 15;
    const int NCH = KD / 16;

    float4 areg, breg[2];

    auto loadAB = [&](int k0) {
        int k = k0 + ksg;
        const float* src;
        if (KD == 256 && k >= 128)
            src = A1 + (size_t)(row0 + arow) * 128 + (k - 128);
        else
            src = A0 + (size_t)(row0 + arow) * 128 + k;
        areg = *(const float4*)src;
#pragma unroll
        for (int q = 0; q < 2; q++)
            breg[q] = *(const float4*)&W[(size_t)(k0 + bkr) * 128 + bcx + q * 64];
    };
    auto storeAB = [&](int buf, int k0) {
        float vv[4] = {areg.x, areg.y, areg.z, areg.w};
#pragma unroll
        for (int j = 0; j < 4; j++) {
            int kl = ksg + j;
            float x = vv[j];
            x = x > 0.f ? x : expm1f(x);
            As[(buf * 16 + kl) * 64 + arow] = fmaf(x, sc[k0 + kl], sh[k0 + kl]);
        }
#pragma unroll
        for (int q = 0; q < 2; q++)
            *(float4*)&Bs[(buf * 16 + bkr) * 128 + bcx + q * 64] = breg[q];
    };

    float acc[4][8];
#pragma unroll
    for (int i = 0; i < 4; i++)
#pragma unroll
        for (int j = 0; j < 8; j++) acc[i][j] = 0.f;

    loadAB(0);
    __syncthreads();            // sc/sh (+xh2s) ready

    if (MODE == 1) {
        int c = tid & 127, h = tid >> 7;
        float p0 = 0.f, p1 = 0.f, p2 = 0.f, p3 = 0.f;
        for (int kk = h * 64; kk < h * 64 + 64; kk++) {
            float w = Wfold[(size_t)kk * 128 + c];
            p0 = fmaf(xh2s[0 * 128 + kk], w, p0);
            p1 = fmaf(xh2s[1 * 128 + kk], w, p1);
            p2 = fmaf(xh2s[2 * 128 + kk], w, p2);
            p3 = fmaf(xh2s[3 * 128 + kk], w, p3);
        }
        bbp[(h * 4 + 0) * 128 + c] = p0; bbp[(h * 4 + 1) * 128 + c] = p1;
        bbp[(h * 4 + 2) * 128 + c] = p2; bbp[(h * 4 + 3) * 128 + c] = p3;
        __syncthreads();
        if (tid < 128) {
#pragma unroll
            for (int b = 0; b < Bq; b++)
                bbs[b * 128 + tid] = bbp[(0 * 4 + b) * 128 + tid]
                                   + bbp[(1 * 4 + b) * 128 + tid];
        }
    } else if (MODE == 2) {
        int c = tid & 127, h = tid >> 7;
        float p0 = 0.f;
        for (int kk = h * 64; kk < h * 64 + 64; kk++)
            p0 = fmaf(xh2s[kk], Wfold[(size_t)kk * 128 + c], p0);
        bbp[h * 128 + c] = p0;
        __syncthreads();
        if (tid < 128) bbs[tid] = bbp[tid] + bbp[128 + tid];
    }

    storeAB(0, 0);
    __syncthreads();

    for (int ch = 0; ch < NCH; ch++) {
        int nxt = ch + 1;
        if (nxt < NCH) loadAB(nxt * 16);
        int buf = ch & 1;
#pragma unroll
        for (int kk = 0; kk < 16; kk++) {
            float4 a0 = *(const float4*)&As[(buf * 16 + kk) * 64 + ty * 4];
            float4 b0 = *(const float4*)&Bs[(buf * 16 + kk) * 128 + tx * 4];
            float4 b1 = *(const float4*)&Bs[(buf * 16 + kk) * 128 + tx * 4 + 64];
            float av[4] = {a0.x, a0.y, a0.z, a0.w};
            float bv[8] = {b0.x, b0.y, b0.z, b0.w, b1.x, b1.y, b1.z, b1.w};
#pragma unroll
            for (int i = 0; i < 4; i++)
#pragma unroll
                for (int j = 0; j < 8; j++)
                    acc[i][j] = fmaf(av[i], bv[j], acc[i][j]);
        }
        if (nxt < NCH) {
            storeAB(nxt & 1, nxt * 16);
            __syncthreads();
        }
    }

    // ---- epilogue: store output + per-thread stats accumulation ----
    float se[8], qe[8], me[8];
#pragma unroll
    for (int j = 0; j < 8; j++) { se[j] = 0.f; qe[j] = 0.f; me[j] = 0.f; }

#pragma unroll
    for (int i = 0; i < 4; i++) {
        int r = row0 + ty * 4 + i;
        int rb = (MODE == 1) ? (r / Nv) : 0;
        float mk = MSUM ? mask[r] : 0.f;
#pragma unroll
        for (int jh = 0; jh < 2; jh++) {
            int c = tx * 4 + jh * 64;
            float4 o;
            o.x = acc[i][jh * 4 + 0] + bias[c + 0];
            o.y = acc[i][jh * 4 + 1] + bias[c + 1];
            o.z = acc[i][jh * 4 + 2] + bias[c + 2];
            o.w = acc[i][jh * 4 + 3] + bias[c + 3];
            if (MODE != 0) {
                o.x += bbs[rb * 128 + c + 0];
                o.y += bbs[rb * 128 + c + 1];
                o.z += bbs[rb * 128 + c + 2];
                o.w += bbs[rb * 128 + c + 3];
            }
            if (res) {
                const float4 rv = *(const float4*)&res[(size_t)r * 128 + c];
                o.x += rv.x; o.y += rv.y; o.z += rv.z; o.w += rv.w;
            }
            *(float4*)&out[(size_t)r * 128 + c] = o;
            if (statsOut) {
                float ov[4] = {o.x, o.y, o.z, o.w};
#pragma unroll
                for (int jj = 0; jj < 4; jj++) {
                    float e = elu_f(ov[jj]);
                    int idx = jh * 4 + jj;
                    se[idx] += e;
                    qe[idx] = fmaf(e, e, qe[idx]);
                    if (MSUM) me[idx] = fmaf(mk, e, me[idx]);
                }
            }
        }
    }

    if (statsOut) {
        float* SA = As;
        float* SQ = Bs;
        float* SM = Bs + 2048;
        if (MSUM && tx == 0) rbarr[ty] = (row0 + ty * 4) / Nv;
        __syncthreads();
#pragma unroll
        for (int j8 = 0; j8 < 8; j8++) {
            int c = tx * 4 + (j8 & 3) + (j8 >> 2) * 64;
            SA[ty * 128 + c] = se[j8];
            SQ[ty * 128 + c] = qe[j8];
            if (MSUM) SM[ty * 128 + c] = me[j8];
        }
        __syncthreads();
        if (tid < 128) {
            int c = tid;
            double s = 0.0, q = 0.0;
            float m0 = 0.f, m1 = 0.f;
            int rb0 = row0 / Nv;
            int rbL = (row0 + 63) / Nv;
#pragma unroll
            for (int t2 = 0; t2 < 16; t2++) {
                s += (double)SA[t2 * 128 + c];
                q += (double)SQ[t2 * 128 + c];
                if (MSUM) {
                    float mv = SM[t2 * 128 + c];
                    if (rbarr[t2] == rb0) m0 += mv; else m1 += mv;
                }
            }
            atomicAdd(&statsOut[c], s);
            atomicAdd(&statsOut[256 + c], q);
            if (MSUM) {
                atomicAdd(&amOut[rb0 * 128 + c], (double)m0);
                if (rbL != rb0) atomicAdd(&amOut[rbL * 128 + c], (double)m1);
            }
        }
    }
}

// ---- standalone GEMM wrapper ----
template <int KD, int MODE, bool MSUM>
__global__ void __launch_bounds__(256, 3) gemm_kernel(
    const float* A0, const float* A1, const float* W, const float* bias,
    const float* res, float* out, const double* stats,
    const float* gamma, const float* beta, double invR, const double* avgms,
    const float* Wfold, const float* betac,
    double* statsOut, double* amOut, const float* mask) {
    gemm_body<KD, MODE, MSUM>(blockIdx.x, A0, A1, W, bias, res, out, stats,
                              gamma, beta, invR, avgms, Wfold, betac,
                              statsOut, amOut, mask);
}

// ---- FUSED: avg j0 GEMM (blocks [0,nb1)) + spmmB (rest) ----
__global__ void __launch_bounds__(256, 3) fused_j0spmmB_kernel(
    const float* v, float* x1, const float* Wj0, const float* bj0,
    const double* st_j0, const float* gm_j0, const float* bt_j0,
    const double* am0, const float* Wf_j0,
    double* st_j1, double* am1, const float* mask,
    const int* startB, const float2* edgeB, float* msg,
    int nb1) {
    if (blockIdx.x < nb1) {
        gemm_body<128, 1, true>(blockIdx.x, v, nullptr, Wj0, bj0, nullptr, x1,
                                st_j0, gm_j0, bt_j0, 1.0 / RV, am0,
                                Wf_j0, nullptr, st_j1, am1, mask);
    } else {
        spmm_body(blockIdx.x - nb1, startB, edgeB, v, Nv * C, msg, FN * C);
    }
}

// ---- FUSED: avg j1 GEMM (blocks [0,nb1)) + next-layer spmmA (rest) ----
__global__ void __launch_bounds__(256, 3) fused_j1spmmA_kernel(
    const float* x1, float* v, const float* Wj1, const float* bj1,
    const double* st_j1, const float* gm_j1, const float* bt_j1,
    const double* am1, const float* Wf_j1, double* stOut_v,
    const int* startA, const float2* edgeA, const float* f, float* msg,
    int nb1) {
    if (blockIdx.x < nb1) {
        gemm_body<128, 1, false>(blockIdx.x, x1, nullptr, Wj1, bj1, v, v,
                                 st_j1, gm_j1, bt_j1, 1.0 / RV, am1,
                                 Wf_j1, nullptr, stOut_v, nullptr, nullptr);
    } else {
        spmm_body(blockIdx.x - nb1, startA, edgeA, f, FN * C, msg, Nv * C);
    }
}

// ================= final conv =================
__global__ void final_kernel(const float* __restrict__ f,
                             const float* __restrict__ W2,
                             const float* __restrict__ b2,
                             float* __restrict__ out,
                             const double* __restrict__ stats,
                             const float* __restrict__ g2,
                             const float* __restrict__ be2) {
    __shared__ float sc[128], sh[128];
    int tid = threadIdx.x;
    if (tid < 128) {
        const double invR = 1.0 / (double)RF;
        double mean = stats[tid] * invR;
        double var  = stats[256 + tid] * invR - mean * mean;
        if (var < 0.0) var = 0.0;
        double a = (double)g2[tid] * rsqrt(var + (double)EPSV);
        sc[tid] = (float)a;
        sh[tid] = (float)((double)be2[tid] - mean * a);
    }
    __syncthreads();
    int gwarp = blockIdx.x * 8 + (tid >> 5);
    int lane = tid & 31;
    if (gwarp >= RF) return;
    float s = 0.f;
#pragma unroll
    for (int j = 0; j < 4; j++) {
        int k = lane + j * 32;
        float xh = fmaf(elu_f(f[(size_t)gwarp * 128 + k]), sc[k], sh[k]);
        s += xh * W2[k];
    }
#pragma unroll
    for (int off = 16; off; off >>= 1) s += __shfl_down_sync(0xffffffffu, s, off);
    if (lane == 0) out[gwarp] = s + b2[0];
}

// ================= host orchestration =================
extern "C" void kernel_launch(void* const* d_in, const int* in_sizes, int n_in,
                              void* d_out, int out_size) {
    const float* inputs   = (const float*)d_in[0];
    const float* mask     = (const float*)d_in[1];
    const int*   Di_rows  = (const int*)d_in[2];
    const int*   Di_cols  = (const int*)d_in[3];
    const float* Di_vals  = (const float*)d_in[4];
    const int*   DiA_rows = (const int*)d_in[5];
    const int*   DiA_cols = (const int*)d_in[6];
    const float* DiA_vals = (const float*)d_in[7];
    const float* W1       = (const float*)d_in[8];
    const float* b1       = (const float*)d_in[9];
    const float* rn_gamma = (const float*)d_in[10];
    const float* rn_beta  = (const float*)d_in[11];
    const float* rn_W     = (const float*)d_in[12];
    const float* rn_b     = (const float*)d_in[13];
    const float* g2       = (const float*)d_in[14];
    const float* be2      = (const float*)d_in[15];
    const float* W2       = (const float*)d_in[16];
    const float* b2       = (const float*)d_in[17];
    float* out = (float*)d_out;

    float *v, *f, *msg, *x1;
    double *statsAll;
    int *cnt2, *startA, *startB;
    float2 *edgeA, *edgeB;
    cudaGetSymbolAddress((void**)&v, g_v);
    cudaGetSymbolAddress((void**)&f, g_f);
    cudaGetSymbolAddress((void**)&msg, g_msg);
    cudaGetSymbolAddress((void**)&x1, g_x1);
    cudaGetSymbolAddress((void**)&statsAll, g_statsAll);
    cudaGetSymbolAddress((void**)&cnt2, g_cnt2);
    cudaGetSymbolAddress((void**)&startA, g_startA);
    cudaGetSymbolAddress((void**)&startB, g_startB);
    cudaGetSymbolAddress((void**)&edgeA, g_edgeA);
    cudaGetSymbolAddress((void**)&edgeB, g_edgeB);

    double* avgmsL = statsAll + 33 * 512;
    auto slot = [&](int c) { return statsAll + (size_t)c * 512; };

    // ---- prologue ----
    cudaMemsetAsync(statsAll, 0, (33 * 512 + 16 * 512) * sizeof(double), 0);
    conv1_kernel<<<RV / 64, 128>>>(inputs, W1, b1, slot(0));
    masksum_kernel<<<Bq, 256>>>(mask);
    cudaMemsetAsync(cnt2, 0, 2 * BINS * sizeof(int), 0);
    hist2_kernel<<<2 * NNZ / 256, 256>>>(DiA_rows, Di_rows);
    scan_block2_kernel<<<192, 1024>>>();
    scan_top2_kernel<<<2, 32>>>();
    scan_finish2_kernel<<<192, 1024>>>(startA, startB);
    fill2_kernel<<<2 * NNZ / 256, 256>>>(DiA_rows, DiA_cols, DiA_vals,
                                         Di_rows, Di_cols, Di_vals,
                                         edgeA, edgeB);

    for (int p = 0; p < 8; p++) {
        int d = 2 * p;
        const float* Wd  = rn_W + (size_t)d * 2 * 256 * 128;
        const float* bd  = rn_b + (size_t)d * 2 * 128;
        const float* gmd = rn_gamma + (size_t)d * 2 * 256;
        const float* btd = rn_beta + (size_t)d * 2 * 256;
        const float* Wa  = rn_W + (size_t)(d + 1) * 2 * 256 * 128;
        const float* ba  = rn_b + (size_t)(d + 1) * 2 * 128;
        const float* gma = rn_gamma + (size_t)(d + 1) * 2 * 256;
        const float* bta = rn_beta + (size_t)(d + 1) * 2 * 256;
        double* am0 = avgmsL + (size_t)p * 1024;
        double* am1 = am0 + 512;

        // ---- dir conv0 ----
        if (p == 0) {
            // msg == 0: const-fold second half (KD=128 live over v)
            gemm_kernel<128, 2, true><<<RV / 64, 256, SMEM_DYN>>>(
                v, nullptr, Wd, bd, v, v,
                slot(0), gmd, btd, 1.0 / RV, nullptr,
                Wd + 128 * 128, btd + 128,
                slot(2), am0, mask);
        } else {
            statsm_kernel<<<RV / 64, 128>>>(msg, slot(2 * d));
            gemm_kernel<256, 0, true><<<RV / 64, 256, SMEM_DYN>>>(
                v, msg, Wd, bd, v, v,
                slot(2 * d), gmd, btd, 1.0 / RV, nullptr,
                nullptr, nullptr,
                slot(2 * d + 2), am0, mask);
        }

        // ---- FUSED: avg j0 (x1) + spmmB (msg = Di @ v) ----
        fused_j0spmmB_kernel<<<RV / 64 + RF / 8, 256, SMEM_DYN>>>(
            v, x1, Wa, ba,
            slot(2 * d + 2), gma, bta,
            am0, Wa + 128 * 128,
            slot(2 * d + 3), am1, mask,
            startB, edgeB, msg,
            RV / 64);

        statsm_kernel<<<RF / 64, 128>>>(msg, slot(2 * d + 1));

        // ---- dir conv1 ----
        double* fOut = (p == 7) ? slot(32) : slot(2 * d + 5);
        if (p == 0) {
            // f == 0: const-fold first half (KD=128 live over msg)
            gemm_kernel<128, 2, false><<<RF / 64, 256, SMEM_DYN>>>(
                msg, nullptr, Wd + 256 * 128 + 128 * 128, bd + 128, nullptr, f,
                slot(1) + 128, gmd + 256 + 128, btd + 256 + 128, 1.0 / RF,
                nullptr,
                Wd + 256 * 128, btd + 256,
                fOut, nullptr, nullptr);
        } else {
            gemm_kernel<256, 0, false><<<RF / 64, 256, SMEM_DYN>>>(
                f, msg, Wd + 256 * 128, bd + 128, nullptr, f,
                slot(2 * d + 1), gmd + 256, btd + 256, 1.0 / RF, nullptr,
                nullptr, nullptr,
                fOut, nullptr, nullptr);
        }

        // ---- avg j1 (v) [+ next pair's spmmA] ----
        if (p < 7) {
            fused_j1spmmA_kernel<<<RV / 64 + RV / 8, 256, SMEM_DYN>>>(
                x1, v, Wa + 256 * 128, ba + 128,
                slot(2 * d + 3), gma + 256, bta + 256,
                am1, Wa + 256 * 128 + 128 * 128, slot(2 * d + 4),
                startA, edgeA, f, msg,
                RV / 64);
        } else {
            gemm_kernel<128, 1, false><<<RV / 64, 256, SMEM_DYN>>>(
                x1, nullptr, Wa + 256 * 128, ba + 128, v, v,
                slot(2 * d + 3), gma + 256, bta + 256, 1.0 / RV, am1,
                Wa + 256 * 128 + 128 * 128, nullptr,
                nullptr, nullptr, nullptr);
        }
    }

    // final conv (stats in slot 32 from pair-7 dir conv1)
    final_kernel<<<RF / 8, 256>>>(f, W2, b2, out, slot(32), g2, be2);
}

// round 15
// speedup vs baseline: 1.0565x; 1.0565x over previous
#include <cuda_runtime.h>
#include <math.h>
#include <stdint.h>

#define Bq 4
#define Nv 12000
#define FN 24000
#define C 128
#define NNZ (48 * FN)     // 1,152,000
#define EPSV 1e-5f

#define RV (Bq * Nv)      // 48000 vertex rows
#define RF (Bq * FN)      // 96000 face rows

#define BINS 98304        // 96 * 1024 (covers 96000 rows)
#define SMEM_DYN 34880    // dynamic smem union for gemm_body

// ---------------- scratch (device globals: allocation-free) ----------------
__device__ float  g_v[RV * C];
__device__ float  g_f[RF * C];
__device__ float  g_msg[RF * C];
__device__ float  g_x1[RV * C];                 // avg-block j0 output
__device__ double g_statsAll[33 * 512 + 16 * 512]; // statsL[33] then avgmsL[16]
__device__ double g_msum[Bq];                   // per-batch mask sums

// CSR build scratch (doubled: [0,BINS)=A, [BINS,2*BINS)=B)
__device__ int    g_cnt2[2 * BINS];
__device__ int    g_incl2[2 * BINS];
__device__ int    g_bsum2[192];
__device__ int    g_cursor2[2 * BINS];
__device__ int    g_startA[BINS + 1];
__device__ int    g_startB[BINS + 1];
__device__ float2 g_edgeA[NNZ];
__device__ float2 g_edgeB[NNZ];

__device__ __forceinline__ float elu_f(float x) {
    return x > 0.f ? x : expm1f(x);
}

// ================= fused dual-CSR build =================
__global__ void hist2_kernel(const int* __restrict__ rowsA,
                             const int* __restrict__ rowsB) {
    int i = blockIdx.x * blockDim.x + threadIdx.x;
    if (i < NNZ) atomicAdd(&g_cnt2[rowsA[i]], 1);
    else         atomicAdd(&g_cnt2[BINS + rowsB[i - NNZ]], 1);
}

__global__ void scan_block2_kernel() {
    __shared__ int sd[1024];
    int t = threadIdx.x;
    int gid = blockIdx.x * 1024 + t;
    sd[t] = g_cnt2[gid];
    __syncthreads();
    for (int off = 1; off < 1024; off <<= 1) {
        int add = (t >= off) ? sd[t - off] : 0;
        __syncthreads();
        sd[t] += add;
        __syncthreads();
    }
    g_incl2[gid] = sd[t];
    if (t == 1023) g_bsum2[blockIdx.x] = sd[1023];
}

__global__ void scan_top2_kernel() {
    int h = blockIdx.x;                   // 0 = A, 1 = B
    if (threadIdx.x == 0) {
        int run = 0;
        for (int b = h * 96; b < h * 96 + 96; b++) {
            int tt = g_bsum2[b]; g_bsum2[b] = run; run += tt;
        }
    }
}

__global__ void scan_finish2_kernel(int* __restrict__ startA,
                                    int* __restrict__ startB) {
    int t = threadIdx.x;
    int gid = blockIdx.x * 1024 + t;
    int half = gid >= BINS;
    int lid_ = gid - half * BINS;
    int* start = half ? startB : startA;
    int excl = g_incl2[gid] - g_cnt2[gid] + g_bsum2[blockIdx.x];
    start[lid_] = excl;
    g_cursor2[gid] = excl;
    if (lid_ == BINS - 1) start[BINS] = excl + g_cnt2[gid];
}

__global__ void fill2_kernel(const int* __restrict__ rowsA,
                             const int* __restrict__ colsA,
                             const float* __restrict__ valsA,
                             const int* __restrict__ rowsB,
                             const int* __restrict__ colsB,
                             const float* __restrict__ valsB,
                             float2* __restrict__ edgesA,
                             float2* __restrict__ edgesB) {
    int i = blockIdx.x * blockDim.x + threadIdx.x;
    if (i < NNZ) {
        int pos = atomicAdd(&g_cursor2[rowsA[i]], 1);
        edgesA[pos] = make_float2(valsA[i], __int_as_float(colsA[i]));
    } else {
        int j = i - NNZ;
        int pos = atomicAdd(&g_cursor2[BINS + rowsB[j]], 1);
        edgesB[pos] = make_float2(valsB[j], __int_as_float(colsB[j]));
    }
}

// ================= SpMM (CSR, atomic-free) =================
__global__ void spmm_kernel(const int* __restrict__ start,
                            const float2* __restrict__ edges,
                            const float* __restrict__ in, int inStride,
                            float* __restrict__ out, int outStride) {
    int t = threadIdx.x;
    int r = blockIdx.x * 4 + (t >> 5);
    int lane = t & 31;
    int b = lane >> 3, k4 = lane & 7;
    int s = start[r], e = start[r + 1];
    float4 acc = make_float4(0.f, 0.f, 0.f, 0.f);
    const float* inb = in + (size_t)b * inStride;
    for (int i = s; i < e; i++) {
        float2 ed = edges[i];
        int c = __float_as_int(ed.y);
        float4 q = *(const float4*)&inb[c * 32 + k4 * 4];
        acc.x = fmaf(ed.x, q.x, acc.x);
        acc.y = fmaf(ed.x, q.y, acc.y);
        acc.z = fmaf(ed.x, q.z, acc.z);
        acc.w = fmaf(ed.x, q.w, acc.w);
    }
    *(float4*)&out[(size_t)b * outStride + r * 32 + k4 * 4] = acc;
}

// 256-thread SpMM body for fused launches (8 rows per block)
__device__ void spmm_body(int bid, const int* __restrict__ start,
                          const float2* __restrict__ edges,
                          const float* __restrict__ in, int inStride,
                          float* __restrict__ out, int outStride) {
    int r = bid * 8 + (threadIdx.x >> 5);
    int lane = threadIdx.x & 31;
    int b = lane >> 3, k4 = lane & 7;
    int s = start[r], e = start[r + 1];
    float4 acc = make_float4(0.f, 0.f, 0.f, 0.f);
    const float* inb = in + (size_t)b * inStride;
    for (int i = s; i < e; i++) {
        float2 ed = edges[i];
        int c = __float_as_int(ed.y);
        float4 q = *(const float4*)&inb[c * 32 + k4 * 4];
        acc.x = fmaf(ed.x, q.x, acc.x);
        acc.y = fmaf(ed.x, q.y, acc.y);
        acc.z = fmaf(ed.x, q.z, acc.z);
        acc.w = fmaf(ed.x, q.w, acc.w);
    }
    *(float4*)&out[(size_t)b * outStride + r * 32 + k4 * 4] = acc;
}

// ================= conv1 (fused stats -> slot0 first half) =================
__global__ void conv1_kernel(const float* __restrict__ in,
                             const float* __restrict__ W1,
                             const float* __restrict__ b1,
                             double* __restrict__ st) {
    int c = threadIdx.x;                  // 128
    int r0 = blockIdx.x * 64;
    float w0 = W1[c], w1 = W1[128 + c], w2 = W1[256 + c], bb = b1[c];
    float s = 0.f, q = 0.f;
    for (int i = 0; i < 64; i++) {
        int r = r0 + i;
        float x0 = in[r * 3 + 0], x1 = in[r * 3 + 1], x2 = in[r * 3 + 2];
        float val = fmaf(x0, w0, fmaf(x1, w1, fmaf(x2, w2, bb)));
        g_v[(size_t)r * 128 + c] = val;
        float e = elu_f(val);
        s += e; q += e * e;
    }
    atomicAdd(&st[c], (double)s);
    atomicAdd(&st[256 + c], (double)q);
}

// ================= slim stats over msg (second-half channels) =================
__global__ void statsm_kernel(const float* __restrict__ x,
                              double* __restrict__ st) {
    int c = threadIdx.x;                  // 128
    int r0 = blockIdx.x * 64;
    float s = 0.f, q = 0.f;
    for (int i = 0; i < 64; i++) {
        float e = elu_f(x[(size_t)(r0 + i) * 128 + c]);
        s += e; q += e * e;
    }
    atomicAdd(&st[128 + c], (double)s);
    atomicAdd(&st[384 + c], (double)q);
}

// ================= per-batch mask sums =================
__global__ void masksum_kernel(const float* __restrict__ mask) {
    __shared__ float sd[256];
    int b = blockIdx.x, t = threadIdx.x;
    float s = 0.f;
    for (int i = t; i < Nv; i += 256) s += mask[b * Nv + i];
    sd[t] = s;
    __syncthreads();
    for (int off = 128; off; off >>= 1) {
        if (t < off) sd[t] += sd[t + off];
        __syncthreads();
    }
    if (t == 0) g_msum[b] = (double)sd[0];
}

// ================= GEMM body: 64x128 tile, 256 threads =================
// MODE 0: plain KD-channel GEMM.
// MODE 1 (avg): KD=128 live; channels 128-255 are per-batch broadcast consts
//   (analytic from avgms); folded into per-batch bias bb via Wfold.
// MODE 2 (const): KD=128 live; other half is constant beta_c (input == 0);
//   folded into batch-uniform bias via Wfold.
template <int KD, int MODE, bool MSUM>
__device__ void gemm_body(
    int bid,
    const float* __restrict__ A0, const float* __restrict__ A1,
    const float* __restrict__ W, const float* __restrict__ bias,
    const float* __restrict__ res, float* __restrict__ out,
    const double* __restrict__ stats,
    const float* __restrict__ gamma, const float* __restrict__ beta,
    double invR, const double* __restrict__ avgms,
    const float* __restrict__ Wfold, const float* __restrict__ betac,
    double* __restrict__ statsOut, double* __restrict__ amOut,
    const float* __restrict__ mask) {
    extern __shared__ char sm[];
    float* As   = (float*)sm;
    float* Bs   = (float*)(sm + 8192);
    float* sc   = (float*)(sm + 24576);
    float* sh   = (float*)(sm + 25600);
    float* xh2s = (float*)(sm + 26624);
    float* bbp  = (float*)(sm + 28672);
    float* bbs  = (float*)(sm + 32768);
    int*   rbarr = (int*)(sm + 34816);
    const int tid = threadIdx.x;
    const int row0 = bid * 64;

    if (tid < KD) {
        double mean = stats[tid] * invR;
        double var  = stats[256 + tid] * invR - mean * mean;
        if (var < 0.0) var = 0.0;
        double a = (double)gamma[tid] * rsqrt(var + (double)EPSV);
        sc[tid] = (float)a;
        sh[tid] = (float)((double)beta[tid] - mean * a);
    }
    if (MODE == 1 && tid < 128) {
        float af[Bq];
        double s = 0.0, sq = 0.0;
        for (int b = 0; b < Bq; b++) {
            af[b] = (float)(avgms[b * 128 + tid] / g_msum[b]);
            double m = (double)af[b];
            s  += m * (double)Nv;
            sq += m * m * (double)Nv;
        }
        double mean = s * (1.0 / (double)RV);
        double var  = sq * (1.0 / (double)RV) - mean * mean;
        if (var < 0.0) var = 0.0;
        double a = (double)gamma[128 + tid] * rsqrt(var + (double)EPSV);
        float sck = (float)a;
        float shk = (float)((double)beta[128 + tid] - mean * a);
#pragma unroll
        for (int b = 0; b < Bq; b++) xh2s[b * 128 + tid] = fmaf(af[b], sck, shk);
    }
    if (MODE == 2 && tid < 128) {
        xh2s[tid] = betac[tid];
    }

    const int arow = tid & 63;
    const int ksg  = (tid >> 6) * 4;
    const int bkr  = tid >> 4;
    const int bcx  = (tid & 15) * 4;
    const int ty = tid >> 4, tx = tid & 15;
    const int NCH = KD / 16;

    float4 areg, breg[2];

    auto loadAB = [&](int k0) {
        int k = k0 + ksg;
        const float* src;
        if (KD == 256 && k >= 128)
            src = A1 + (size_t)(row0 + arow) * 128 + (k - 128);
        else
            src = A0 + (size_t)(row0 + arow) * 128 + k;
        areg = *(const float4*)src;
#pragma unroll
        for (int q = 0; q < 2; q++)
            breg[q] = *(const float4*)&W[(size_t)(k0 + bkr) * 128 + bcx + q * 64];
    };
    auto storeAB = [&](int buf, int k0) {
        float vv[4] = {areg.x, areg.y, areg.z, areg.w};
#pragma unroll
        for (int j = 0; j < 4; j++) {
            int kl = ksg + j;
            float x = vv[j];
            x = x > 0.f ? x : expm1f(x);
            As[(buf * 16 + kl) * 64 + arow] = fmaf(x, sc[k0 + kl], sh[k0 + kl]);
        }
#pragma unroll
        for (int q = 0; q < 2; q++)
            *(float4*)&Bs[(buf * 16 + bkr) * 128 + bcx + q * 64] = breg[q];
    };

    float acc[4][8];
#pragma unroll
    for (int i = 0; i < 4; i++)
#pragma unroll
        for (int j = 0; j < 8; j++) acc[i][j] = 0.f;

    loadAB(0);
    __syncthreads();

    if (MODE == 1) {
        int c = tid & 127, h = tid >> 7;
        float p0 = 0.f, p1 = 0.f, p2 = 0.f, p3 = 0.f;
        for (int kk = h * 64; kk < h * 64 + 64; kk++) {
            float w = Wfold[(size_t)kk * 128 + c];
            p0 = fmaf(xh2s[0 * 128 + kk], w, p0);
            p1 = fmaf(xh2s[1 * 128 + kk], w, p1);
            p2 = fmaf(xh2s[2 * 128 + kk], w, p2);
            p3 = fmaf(xh2s[3 * 128 + kk], w, p3);
        }
        bbp[(h * 4 + 0) * 128 + c] = p0; bbp[(h * 4 + 1) * 128 + c] = p1;
        bbp[(h * 4 + 2) * 128 + c] = p2; bbp[(h * 4 + 3) * 128 + c] = p3;
        __syncthreads();
        if (tid < 128) {
#pragma unroll
            for (int b = 0; b < Bq; b++)
                bbs[b * 128 + tid] = bbp[(0 * 4 + b) * 128 + tid]
                                   + bbp[(1 * 4 + b) * 128 + tid];
        }
    } else if (MODE == 2) {
        int c = tid & 127, h = tid >> 7;
        float p0 = 0.f;
        for (int kk = h * 64; kk < h * 64 + 64; kk++)
            p0 = fmaf(xh2s[kk], Wfold[(size_t)kk * 128 + c], p0);
        bbp[h * 128 + c] = p0;
        __syncthreads();
        if (tid < 128) bbs[tid] = bbp[tid] + bbp[128 + tid];
    }

    storeAB(0, 0);
    __syncthreads();

    for (int ch = 0; ch < NCH; ch++) {
        int nxt = ch + 1;
        if (nxt < NCH) loadAB(nxt * 16);
        int buf = ch & 1;
#pragma unroll
        for (int kk = 0; kk < 16; kk++) {
            float4 a0 = *(const float4*)&As[(buf * 16 + kk) * 64 + ty * 4];
            float4 b0 = *(const float4*)&Bs[(buf * 16 + kk) * 128 + tx * 4];
            float4 b1 = *(const float4*)&Bs[(buf * 16 + kk) * 128 + tx * 4 + 64];
            float av[4] = {a0.x, a0.y, a0.z, a0.w};
            float bv[8] = {b0.x, b0.y, b0.z, b0.w, b1.x, b1.y, b1.z, b1.w};
#pragma unroll
            for (int i = 0; i < 4; i++)
#pragma unroll
                for (int j = 0; j < 8; j++)
                    acc[i][j] = fmaf(av[i], bv[j], acc[i][j]);
        }
        if (nxt < NCH) {
            storeAB(nxt & 1, nxt * 16);
            __syncthreads();
        }
    }

    // ---- epilogue: store output + per-thread stats accumulation ----
    float se[8], qe[8], me[8];
#pragma unroll
    for (int j = 0; j < 8; j++) { se[j] = 0.f; qe[j] = 0.f; me[j] = 0.f; }

#pragma unroll
    for (int i = 0; i < 4; i++) {
        int r = row0 + ty * 4 + i;
        int rb = (MODE == 1) ? (r / Nv) : 0;
        float mk = MSUM ? mask[r] : 0.f;
#pragma unroll
        for (int jh = 0; jh < 2; jh++) {
            int c = tx * 4 + jh * 64;
            float4 o;
            o.x = acc[i][jh * 4 + 0] + bias[c + 0];
            o.y = acc[i][jh * 4 + 1] + bias[c + 1];
            o.z = acc[i][jh * 4 + 2] + bias[c + 2];
            o.w = acc[i][jh * 4 + 3] + bias[c + 3];
            if (MODE != 0) {
                o.x += bbs[rb * 128 + c + 0];
                o.y += bbs[rb * 128 + c + 1];
                o.z += bbs[rb * 128 + c + 2];
                o.w += bbs[rb * 128 + c + 3];
            }
            if (res) {
                const float4 rv = *(const float4*)&res[(size_t)r * 128 + c];
                o.x += rv.x; o.y += rv.y; o.z += rv.z; o.w += rv.w;
            }
            *(float4*)&out[(size_t)r * 128 + c] = o;
            if (statsOut) {
                float ov[4] = {o.x, o.y, o.z, o.w};
#pragma unroll
                for (int jj = 0; jj < 4; jj++) {
                    float e = elu_f(ov[jj]);
                    int idx = jh * 4 + jj;
                    se[idx] += e;
                    qe[idx] = fmaf(e, e, qe[idx]);
                    if (MSUM) me[idx] = fmaf(mk, e, me[idx]);
                }
            }
        }
    }

    if (statsOut) {
        float* SA = As;
        float* SQ = Bs;
        float* SM = Bs + 2048;
        if (MSUM && tx == 0) rbarr[ty] = (row0 + ty * 4) / Nv;
        __syncthreads();
#pragma unroll
        for (int j8 = 0; j8 < 8; j8++) {
            int c = tx * 4 + (j8 & 3) + (j8 >> 2) * 64;
            SA[ty * 128 + c] = se[j8];
            SQ[ty * 128 + c] = qe[j8];
            if (MSUM) SM[ty * 128 + c] = me[j8];
        }
        __syncthreads();
        if (tid < 128) {
            int c = tid;
            double s = 0.0, q = 0.0;
            float m0 = 0.f, m1 = 0.f;
            int rb0 = row0 / Nv;
            int rbL = (row0 + 63) / Nv;
#pragma unroll
            for (int t2 = 0; t2 < 16; t2++) {
                s += (double)SA[t2 * 128 + c];
                q += (double)SQ[t2 * 128 + c];
                if (MSUM) {
                    float mv = SM[t2 * 128 + c];
                    if (rbarr[t2] == rb0) m0 += mv; else m1 += mv;
                }
            }
            atomicAdd(&statsOut[c], s);
            atomicAdd(&statsOut[256 + c], q);
            if (MSUM) {
                atomicAdd(&amOut[rb0 * 128 + c], (double)m0);
                if (rbL != rb0) atomicAdd(&amOut[rbL * 128 + c], (double)m1);
            }
        }
    }
}

// ---- standalone GEMM wrapper ----
template <int KD, int MODE, bool MSUM>
__global__ void __launch_bounds__(256, 3) gemm_kernel(
    const float* A0, const float* A1, const float* W, const float* bias,
    const float* res, float* out, const double* stats,
    const float* gamma, const float* beta, double invR, const double* avgms,
    const float* Wfold, const float* betac,
    double* statsOut, double* amOut, const float* mask) {
    gemm_body<KD, MODE, MSUM>(blockIdx.x, A0, A1, W, bias, res, out, stats,
                              gamma, beta, invR, avgms, Wfold, betac,
                              statsOut, amOut, mask);
}

// ---- FUSED: dir conv1 GEMM (blocks [0,nb1)) + avg j0 GEMM (rest) ----
__global__ void __launch_bounds__(256, 3) fused_g1j0_kernel(
    // dir conv1 (KD=256, MODE0)
    const float* f, const float* msg, const float* Wc1, const float* bc1,
    const double* st_c1, const float* gm_c1, const float* bt_c1,
    double* stOut_c1,
    // avg j0 (KD=128, MODE1, MSUM)
    const float* v, float* x1, const float* Wj0, const float* bj0,
    const double* st_j0, const float* gm_j0, const float* bt_j0,
    const double* am0, const float* Wf_j0,
    double* st_j1, double* am1, const float* mask,
    int nb1) {
    if (blockIdx.x < nb1) {
        gemm_body<256, 0, false>(blockIdx.x, f, msg, Wc1, bc1, nullptr,
                                 (float*)f, st_c1, gm_c1, bt_c1,
                                 1.0 / RF, nullptr, nullptr, nullptr,
                                 stOut_c1, nullptr, nullptr);
    } else {
        gemm_body<128, 1, true>(blockIdx.x - nb1, v, nullptr, Wj0, bj0,
                                nullptr, x1, st_j0, gm_j0, bt_j0,
                                1.0 / RV, am0, Wf_j0, nullptr,
                                st_j1, am1, mask);
    }
}

// ---- FUSED: avg j1 GEMM (blocks [0,nb1)) + next-layer spmmA (rest) ----
__global__ void __launch_bounds__(256, 3) fused_j1spmmA_kernel(
    const float* x1, float* v, const float* Wj1, const float* bj1,
    const double* st_j1, const float* gm_j1, const float* bt_j1,
    const double* am1, const float* Wf_j1, double* stOut_v,
    const int* startA, const float2* edgeA, const float* f, float* msg,
    int nb1) {
    if (blockIdx.x < nb1) {
        gemm_body<128, 1, false>(blockIdx.x, x1, nullptr, Wj1, bj1, v, v,
                                 st_j1, gm_j1, bt_j1, 1.0 / RV, am1,
                                 Wf_j1, nullptr, stOut_v, nullptr, nullptr);
    } else {
        spmm_body(blockIdx.x - nb1, startA, edgeA, f, FN * C, msg, Nv * C);
    }
}

// ================= final conv =================
__global__ void final_kernel(const float* __restrict__ f,
                             const float* __restrict__ W2,
                             const float* __restrict__ b2,
                             float* __restrict__ out,
                             const double* __restrict__ stats,
                             const float* __restrict__ g2,
                             const float* __restrict__ be2) {
    __shared__ float sc[128], sh[128];
    int tid = threadIdx.x;
    if (tid < 128) {
        const double invR = 1.0 / (double)RF;
        double mean = stats[tid] * invR;
        double var  = stats[256 + tid] * invR - mean * mean;
        if (var < 0.0) var = 0.0;
        double a = (double)g2[tid] * rsqrt(var + (double)EPSV);
        sc[tid] = (float)a;
        sh[tid] = (float)((double)be2[tid] - mean * a);
    }
    __syncthreads();
    int gwarp = blockIdx.x * 8 + (tid >> 5);
    int lane = tid & 31;
    if (gwarp >= RF) return;
    float s = 0.f;
#pragma unroll
    for (int j = 0; j < 4; j++) {
        int k = lane + j * 32;
        float xh = fmaf(elu_f(f[(size_t)gwarp * 128 + k]), sc[k], sh[k]);
        s += xh * W2[k];
    }
#pragma unroll
    for (int off = 16; off; off >>= 1) s += __shfl_down_sync(0xffffffffu, s, off);
    if (lane == 0) out[gwarp] = s + b2[0];
}

// ================= host orchestration =================
extern "C" void kernel_launch(void* const* d_in, const int* in_sizes, int n_in,
                              void* d_out, int out_size) {
    const float* inputs   = (const float*)d_in[0];
    const float* mask     = (const float*)d_in[1];
    const int*   Di_rows  = (const int*)d_in[2];
    const int*   Di_cols  = (const int*)d_in[3];
    const float* Di_vals  = (const float*)d_in[4];
    const int*   DiA_rows = (const int*)d_in[5];
    const int*   DiA_cols = (const int*)d_in[6];
    const float* DiA_vals = (const float*)d_in[7];
    const float* W1       = (const float*)d_in[8];
    const float* b1       = (const float*)d_in[9];
    const float* rn_gamma = (const float*)d_in[10];
    const float* rn_beta  = (const float*)d_in[11];
    const float* rn_W     = (const float*)d_in[12];
    const float* rn_b     = (const float*)d_in[13];
    const float* g2       = (const float*)d_in[14];
    const float* be2      = (const float*)d_in[15];
    const float* W2       = (const float*)d_in[16];
    const float* b2       = (const float*)d_in[17];
    float* out = (float*)d_out;

    float *v, *f, *msg, *x1;
    double *statsAll;
    int *cnt2, *startA, *startB;
    float2 *edgeA, *edgeB;
    cudaGetSymbolAddress((void**)&v, g_v);
    cudaGetSymbolAddress((void**)&f, g_f);
    cudaGetSymbolAddress((void**)&msg, g_msg);
    cudaGetSymbolAddress((void**)&x1, g_x1);
    cudaGetSymbolAddress((void**)&statsAll, g_statsAll);
    cudaGetSymbolAddress((void**)&cnt2, g_cnt2);
    cudaGetSymbolAddress((void**)&startA, g_startA);
    cudaGetSymbolAddress((void**)&startB, g_startB);
    cudaGetSymbolAddress((void**)&edgeA, g_edgeA);
    cudaGetSymbolAddress((void**)&edgeB, g_edgeB);

    double* avgmsL = statsAll + 33 * 512;
    auto slot = [&](int c) { return statsAll + (size_t)c * 512; };

    // ---- prologue ----
    cudaMemsetAsync(statsAll, 0, (33 * 512 + 16 * 512) * sizeof(double), 0);
    conv1_kernel<<<RV / 64, 128>>>(inputs, W1, b1, slot(0));
    masksum_kernel<<<Bq, 256>>>(mask);
    cudaMemsetAsync(cnt2, 0, 2 * BINS * sizeof(int), 0);
    hist2_kernel<<<2 * NNZ / 256, 256>>>(DiA_rows, Di_rows);
    scan_block2_kernel<<<192, 1024>>>();
    scan_top2_kernel<<<2, 32>>>();
    scan_finish2_kernel<<<192, 1024>>>(startA, startB);
    fill2_kernel<<<2 * NNZ / 256, 256>>>(DiA_rows, DiA_cols, DiA_vals,
                                         Di_rows, Di_cols, Di_vals,
                                         edgeA, edgeB);

    for (int p = 0; p < 8; p++) {
        int d = 2 * p;
        const float* Wd  = rn_W + (size_t)d * 2 * 256 * 128;
        const float* bd  = rn_b + (size_t)d * 2 * 128;
        const float* gmd = rn_gamma + (size_t)d * 2 * 256;
        const float* btd = rn_beta + (size_t)d * 2 * 256;
        const float* Wa  = rn_W + (size_t)(d + 1) * 2 * 256 * 128;
        const float* ba  = rn_b + (size_t)(d + 1) * 2 * 128;
        const float* gma = rn_gamma + (size_t)(d + 1) * 2 * 256;
        const float* bta = rn_beta + (size_t)(d + 1) * 2 * 256;
        double* am0 = avgmsL + (size_t)p * 1024;
        double* am1 = am0 + 512;

        // ---- dir conv0 (v += conv) ----
        if (p == 0) {
            // msg == 0: const-fold second half (KD=128 live over v)
            gemm_kernel<128, 2, true><<<RV / 64, 256, SMEM_DYN>>>(
                v, nullptr, Wd, bd, v, v,
                slot(0), gmd, btd, 1.0 / RV, nullptr,
                Wd + 128 * 128, btd + 128,
                slot(2), am0, mask);
        } else {
            statsm_kernel<<<RV / 64, 128>>>(msg, slot(2 * d));
            gemm_kernel<256, 0, true><<<RV / 64, 256, SMEM_DYN>>>(
                v, msg, Wd, bd, v, v,
                slot(2 * d), gmd, btd, 1.0 / RV, nullptr,
                nullptr, nullptr,
                slot(2 * d + 2), am0, mask);
        }

        // ---- spmmB (critical path: launch immediately after gemm0) ----
        spmm_kernel<<<RF / 4, 128>>>(startB, edgeB, v, Nv * C, msg, FN * C);
        statsm_kernel<<<RF / 64, 128>>>(msg, slot(2 * d + 1));

        // ---- dir conv1 (f) [+ avg j0 (x1) tail-filling] ----
        double* fOut = (p == 7) ? slot(32) : slot(2 * d + 5);
        if (p == 0) {
            // f == 0: const-fold first half (KD=128 live over msg)
            gemm_kernel<128, 2, false><<<RF / 64, 256, SMEM_DYN>>>(
                msg, nullptr, Wd + 256 * 128 + 128 * 128, bd + 128, nullptr, f,
                slot(1) + 128, gmd + 256 + 128, btd + 256 + 128, 1.0 / RF,
                nullptr,
                Wd + 256 * 128, btd + 256,
                fOut, nullptr, nullptr);
            gemm_kernel<128, 1, true><<<RV / 64, 256, SMEM_DYN>>>(
                v, nullptr, Wa, ba, nullptr, x1,
                slot(2), gma, bta, 1.0 / RV, am0,
                Wa + 128 * 128, nullptr,
                slot(3), am1, mask);
        } else {
            fused_g1j0_kernel<<<RF / 64 + RV / 64, 256, SMEM_DYN>>>(
                f, msg, Wd + 256 * 128, bd + 128,
                slot(2 * d + 1), gmd + 256, btd + 256, fOut,
                v, x1, Wa, ba,
                slot(2 * d + 2), gma, bta,
                am0, Wa + 128 * 128,
                slot(2 * d + 3), am1, mask,
                RF / 64);
        }

        // ---- avg j1 (v) [+ next pair's spmmA] ----
        if (p < 7) {
            fused_j1spmmA_kernel<<<RV / 64 + RV / 8, 256, SMEM_DYN>>>(
                x1, v, Wa + 256 * 128, ba + 128,
                slot(2 * d + 3), gma + 256, bta + 256,
                am1, Wa + 256 * 128 + 128 * 128, slot(2 * d + 4),
                startA, edgeA, f, msg,
                RV / 64);
        } else {
            gemm_kernel<128, 1, false><<<RV / 64, 256, SMEM_DYN>>>(
                x1, nullptr, Wa + 256 * 128, ba + 128, v, v,
                slot(2 * d + 3), gma + 256, bta + 256, 1.0 / RV, am1,
                Wa + 256 * 128 + 128 * 128, nullptr,
                nullptr, nullptr, nullptr);
        }
    }

    // final conv (stats in slot 32 from pair-7 dir conv1)
    final_kernel<<<RF / 8, 256>>>(f, W2, b2, out, slot(32), g2, be2);
}